// round 8
// baseline (speedup 1.0000x reference)
#include <cuda_runtime.h>
#include <cuda_bf16.h>

#define NN 2048
#define RR 4
#define NT 256
#define BR3(j) ((((j)&1)<<2) | ((j)&2) | (((j)&4)>>2))

typedef unsigned long long ull;

// Precomputed filters, storage index fidx = 256v + 32s + c  (k = 256v + 8c + s)
__device__ float2 g_Ghat[RR][NN];
__device__ float2 g_Hhat[RR][NN];
__device__ float2 g_HH[2][NN];
__device__ float2 g_A [2][NN];
__device__ float2 g_B [2][NN];

// ---------------- packed f32x2 complex primitives (sm_103a) ----------------
__device__ __forceinline__ ull PKF(float x, float y){
    ull r; asm("mov.b64 %0, {%1, %2};" : "=l"(r) : "f"(x), "f"(y)); return r;
}
__device__ __forceinline__ void UPK(ull a, float& x, float& y){
    asm("mov.b64 {%0, %1}, %2;" : "=f"(x), "=f"(y) : "l"(a));
}
__device__ __forceinline__ ull padd(ull a, ull b){
    ull r; asm("add.rn.f32x2 %0, %1, %2;" : "=l"(r) : "l"(a), "l"(b)); return r;
}
__device__ __forceinline__ ull psub(ull a, ull b){
    ull r; asm("sub.rn.f32x2 %0, %1, %2;" : "=l"(r) : "l"(a), "l"(b)); return r;
}
__device__ __forceinline__ ull pmul(ull a, ull b){
    ull r; asm("mul.rn.f32x2 %0, %1, %2;" : "=l"(r) : "l"(a), "l"(b)); return r;
}
__device__ __forceinline__ ull pfma(ull a, ull b, ull c){
    ull r; asm("fma.rn.f32x2 %0, %1, %2, %3;" : "=l"(r) : "l"(a), "l"(b), "l"(c)); return r;
}
__device__ __forceinline__ ull splat_x(ull a){ float x,y; UPK(a,x,y); return PKF(x,x); }
__device__ __forceinline__ ull splat_y(ull a){ float x,y; UPK(a,x,y); return PKF(y,y); }
__device__ __forceinline__ ull rotp (ull a){ float x,y; UPK(a,x,y); return PKF(-y, x); }  // * i
__device__ __forceinline__ ull rotm (ull a){ float x,y; UPK(a,x,y); return PKF( y,-x); }  // * -i
__device__ __forceinline__ ull conjp(ull a){ float x,y; UPK(a,x,y); return PKF( x,-y); }
__device__ __forceinline__ ull swapp(ull a){ float x,y; UPK(a,x,y); return PKF( y, x); }
__device__ __forceinline__ ull pcmul(ull a, ull b){   // a*b
    return pfma(splat_x(a), b, pmul(splat_y(a), rotp(b)));
}
__device__ __forceinline__ ull pcmulj(ull a, ull b){  // a*conj(b)
    return pfma(splat_x(a), conjp(b), pmul(splat_y(a), swapp(b)));
}
__device__ __forceinline__ ull pshfl_xor(ull v, int m){
    float x,y; UPK(v,x,y);
    x = __shfl_xor_sync(0xffffffffu, x, m);
    y = __shfl_xor_sync(0xffffffffu, y, m);
    return PKF(x,y);
}
__device__ __forceinline__ int br5(int x){ return (int)(__brev((unsigned)x) >> 27); }

#define R2C 0.70710678118654752440f

struct LaneTw { ull w16, w8, w4; };

__device__ __forceinline__ float2 s_cmul(float2 a, float2 b){
    return make_float2(a.x*b.x - a.y*b.y, a.x*b.y + a.y*b.x);
}
__device__ __forceinline__ float2 s_csqr(float2 a){ return make_float2(a.x*a.x - a.y*a.y, 2.f*a.x*a.y); }

__device__ __forceinline__ LaneTw make_lane_tw(int lane){
    float s, c;
    sincospif((float)(lane & 15) * (1.f/16.f), &s, &c);
    float2 w16 = make_float2(c, -s);
    float2 w8 = s_csqr(w16); if (lane & 8){ w8.x = -w8.x; w8.y = -w8.y; }
    float2 w4 = s_csqr(w8);  if (lane & 4){ w4.x = -w4.x; w4.y = -w4.y; }
    LaneTw T;
    T.w16 = PKF(w16.x, w16.y);
    T.w8  = PKF(w8.x,  w8.y);
    T.w4  = PKF(w4.x,  w4.y);
    return T;
}

// DIF FFT-32 across lanes; input natural (lane = time), output lane l holds X[br5(l)].
__device__ __forceinline__ ull fft32_fwd(ull v, const LaneTw& T, int lane){
    ull p;
    p = pshfl_xor(v, 16);
    v = (lane & 16) ? pcmul(psub(p, v), T.w16) : padd(v, p);
    p = pshfl_xor(v, 8);
    v = (lane & 8)  ? pcmul(psub(p, v), T.w8)  : padd(v, p);
    p = pshfl_xor(v, 4);
    v = (lane & 4)  ? pcmul(psub(p, v), T.w4)  : padd(v, p);
    p = pshfl_xor(v, 2);
    if (lane & 2) { ull d = psub(p, v); v = (lane & 1) ? rotm(d) : d; }
    else            v = padd(v, p);
    p = pshfl_xor(v, 1);
    v = (lane & 1) ? psub(p, v) : padd(v, p);
    return v;
}

// Exact unscaled inverse (input bit-reversed across lanes, output natural, x32).
__device__ __forceinline__ ull fft32_inv(ull v, const LaneTw& T, int lane){
    ull p;
    p = pshfl_xor(v, 1);
    v = (lane & 1) ? psub(p, v) : padd(v, p);
    if ((lane & 2) && (lane & 1)) v = rotp(v);
    p = pshfl_xor(v, 2);
    v = (lane & 2) ? psub(p, v) : padd(v, p);
    if (lane & 4)  v = pcmulj(v, T.w4);
    p = pshfl_xor(v, 4);
    v = (lane & 4) ? psub(p, v) : padd(v, p);
    if (lane & 8)  v = pcmulj(v, T.w8);
    p = pshfl_xor(v, 8);
    v = (lane & 8) ? psub(p, v) : padd(v, p);
    if (lane & 16) v = pcmulj(v, T.w16);
    p = pshfl_xor(v, 16);
    v = (lane & 16) ? psub(p, v) : padd(v, p);
    return v;
}

// Register FFT-8, DIF, output reg j holds X8[br3(j)].
__device__ __forceinline__ void fft8_fwd(ull r[8]){
    const ull R2R2 = PKF(R2C, R2C);
    ull a, d;
    a = r[0]; r[0] = padd(a, r[4]); r[4] = psub(a, r[4]);
    a = r[1]; d = psub(a, r[5]); r[1] = padd(a, r[5]);
              r[5] = pmul(padd(d, rotm(d)), R2R2);            // ((dx+dy)R2,(dy-dx)R2)
    a = r[2]; d = psub(a, r[6]); r[2] = padd(a, r[6]);
              r[6] = rotm(d);                                  // (dy,-dx)
    a = r[3]; d = psub(a, r[7]); r[3] = padd(a, r[7]);
              r[7] = pmul(psub(rotm(d), d), R2R2);             // ((dy-dx)R2,-(dx+dy)R2)
    a = r[0]; r[0] = padd(a, r[2]); r[2] = psub(a, r[2]);
    a = r[1]; d = psub(a, r[3]); r[1] = padd(a, r[3]); r[3] = rotm(d);
    a = r[4]; r[4] = padd(a, r[6]); r[6] = psub(a, r[6]);
    a = r[5]; d = psub(a, r[7]); r[5] = padd(a, r[7]); r[7] = rotm(d);
    a = r[0]; r[0] = padd(a, r[1]); r[1] = psub(a, r[1]);
    a = r[2]; r[2] = padd(a, r[3]); r[3] = psub(a, r[3]);
    a = r[4]; r[4] = padd(a, r[5]); r[5] = psub(a, r[5]);
    a = r[6]; r[6] = padd(a, r[7]); r[7] = psub(a, r[7]);
}

// Exact unscaled inverse of fft8_fwd (input br3 order, output natural, x8).
__device__ __forceinline__ void fft8_inv(ull r[8]){
    const ull R2R2 = PKF(R2C, R2C);
    ull a, d;
    a = r[0]; r[0] = padd(a, r[1]); r[1] = psub(a, r[1]);
    a = r[2]; r[2] = padd(a, r[3]); r[3] = psub(a, r[3]);
    a = r[4]; r[4] = padd(a, r[5]); r[5] = psub(a, r[5]);
    a = r[6]; r[6] = padd(a, r[7]); r[7] = psub(a, r[7]);
    a = r[0]; r[0] = padd(a, r[2]); r[2] = psub(a, r[2]);
    d = rotp(r[3]); a = r[1]; r[1] = padd(a, d); r[3] = psub(a, d);
    a = r[4]; r[4] = padd(a, r[6]); r[6] = psub(a, r[6]);
    d = rotp(r[7]); a = r[5]; r[5] = padd(a, d); r[7] = psub(a, d);
    d = r[4];                                   a = r[0]; r[0] = padd(a, d); r[4] = psub(a, d);
    d = pmul(padd(r[5], rotp(r[5])), R2R2);     a = r[1]; r[1] = padd(a, d); r[5] = psub(a, d);
    d = rotp(r[6]);                             a = r[2]; r[2] = padd(a, d); r[6] = psub(a, d);
    d = pmul(rotp(psub(r[7], rotm(r[7]))), R2R2);
                                                a = r[3]; r[3] = padd(a, d); r[7] = psub(a, d);
}

// ---------------------------------------------------------------------------
// Forward 2048: input xt[t] = time values at n = n0 + 256t (n0 = w + 8*lane);
// output xh[v] = X[k], k = 256v + 8*lane + w.  Uses sm2[2112] transpose buffer.
// ---------------------------------------------------------------------------
__device__ __forceinline__ void fwd2048(ull xt[8], ull xh[8], ull* sm2,
                                        const ull tws[8], ull tw2,
                                        const LaneTw& T, int lane, int w)
{
    fft8_fwd(xt);                               // reg j -> digit s = br3(j)
#pragma unroll
    for (int j = 1; j < 8; j++) xt[j] = pcmul(xt[j], tws[BR3(j)]);
    int c = br5(lane);
    __syncthreads();                            // protect prior readers of sm2
#pragma unroll
    for (int j = 0; j < 8; j++){
        ull v = fft32_fwd(xt[j], T, lane);
        v = pcmul(v, tw2);                      // w_256^{w*br5(lane)}
        sm2[(w*8 + BR3(j))*33 + c] = v;         // (s, c, r=w)
    }
    __syncthreads();
    ull m[8];
#pragma unroll
    for (int rr = 0; rr < 8; rr++) m[rr] = sm2[(rr*8 + w)*33 + lane];
    fft8_fwd(m);
#pragma unroll
    for (int v = 0; v < 8; v++) xh[v] = m[BR3(v)];
}

// Exact unscaled inverse (x2048): input q[v] spectrum, output xt[t] time.
__device__ __forceinline__ void inv2048(ull q[8], ull xt[8], ull* sm2,
                                        const ull tws[8], ull tw2,
                                        const LaneTw& T, int lane, int w)
{
    ull r[8];
#pragma unroll
    for (int j = 0; j < 8; j++) r[j] = q[BR3(j)];
    fft8_inv(r);
    __syncthreads();
#pragma unroll
    for (int rr = 0; rr < 8; rr++) sm2[(rr*8 + w)*33 + lane] = r[rr];
    __syncthreads();
    int c = br5(lane);
    ull rs[8];
#pragma unroll
    for (int s = 0; s < 8; s++){
        ull v = sm2[(w*8 + s)*33 + c];
        v = pcmulj(v, tw2);
        rs[s] = fft32_inv(v, T, lane);
    }
#pragma unroll
    for (int j = 0; j < 8; j++)
        xt[j] = (BR3(j) == 0) ? rs[0] : pcmulj(rs[BR3(j)], tws[BR3(j)]);
    fft8_inv(xt);
}

// Per-thread twiddle setup shared by both FFT kernels.
__device__ __forceinline__ void setup_tws(ull tws[8], ull& tw2, int n0, int lane, int w){
    float s, c;
    sincospif((float)n0*(1.f/1024.f), &s, &c);
    float2 b = make_float2(c, -s);
    float2 cur = make_float2(1.f, 0.f);
    tws[0] = PKF(1.f, 0.f);
#pragma unroll
    for (int j = 1; j < 8; j++){ cur = s_cmul(cur, b); tws[j] = PKF(cur.x, cur.y); }
    sincospif((float)(w*br5(lane))*(1.f/128.f), &s, &c);
    tw2 = PKF(c, -s);
}

// ---------------------------------------------------------------------------
__global__ void __launch_bounds__(NT)
precompute_kernel(const float* __restrict__ G, const float* __restrict__ H)
{
    __shared__ ull sm2[2112];
    float* smf = (float*)sm2;
    int tid = threadIdx.x, lane = tid & 31, w = tid >> 5;
    int n0 = w + 8*lane;
    LaneTw T = make_lane_tw(lane);
    ull tws[8], tw2;
    setup_tws(tws, tw2, n0, lane, w);

    int wb = blockIdx.x;
    const float* src = (wb < RR) ? (G + wb*NN) : (H + (wb-RR)*NN);
    for (int idx = tid; idx < NN; idx += NT) smf[idx + (idx>>5)] = src[idx];
    __syncthreads();

    ull xt[8];
    if (wb < RR){
#pragma unroll
        for (int t = 0; t < 8; t++){
            int n = n0 + 256*t;
            xt[t] = PKF(smf[n + (n>>5)], 0.f);
        }
    } else {
#pragma unroll
        for (int t = 0; t < 8; t++){
            int n = n0 + 256*t;
            int j = (NN - n) & (NN - 1);
            float hv = smf[j + (j>>5)];
            float s, c; sincospif((float)j*(1.f/(float)NN), &s, &c);   // eta^j
            xt[t] = PKF(hv*c, hv*s);
        }
    }
    __syncthreads();

    ull xh[8];
    fwd2048(xt, xh, sm2, tws, tw2, T, lane, w);

    float2* dst = (wb < RR) ? g_Ghat[wb] : g_Hhat[wb - RR];
#pragma unroll
    for (int v = 0; v < 8; v++){
        float x, y; UPK(xh[v], x, y);
        dst[256*v + 32*w + lane] = make_float2(x, y);
    }
}

__global__ void __launch_bounds__(NT)
combine_kernel()
{
    int j = blockIdx.x, tid = threadIdx.x;
    const float cs = 0.5f / (float)NN;
    for (int k = tid; k < NN; k += NT){
        float2 g0 = g_Ghat[2*j][k], g1 = g_Ghat[2*j+1][k];
        float2 h0 = g_Hhat[2*j][k], h1 = g_Hhat[2*j+1][k];
        g_A[j][k]  = make_float2((g0.x + g1.y) * cs, (g0.y - g1.x) * cs);
        g_B[j][k]  = make_float2((g0.x - g1.y) * cs, (g0.y + g1.x) * cs);
        g_HH[j][k] = make_float2(h0.x - h1.y,        h0.y + h1.x);
    }
}

// ---------------------------------------------------------------------------
__global__ void __launch_bounds__(NT)
toeplitz_kernel(const float* __restrict__ x, float* __restrict__ out)
{
    __shared__ ull sm2[2112];
    float* smf = (float*)sm2;
    int tid = threadIdx.x, lane = tid & 31, w = tid >> 5;
    int n0 = w + 8*lane;
    LaneTw T = make_lane_tw(lane);
    ull tws[8], tw2;
    setup_tws(tws, tw2, n0, lane, w);

    ull etaC0, etaP0;
    { float s, c; sincospif((float)n0*(1.f/(float)NN), &s, &c);
      etaC0 = PKF(c, -s); etaP0 = PKF(c, s); }
    const ull STEPC = PKF(0.92387953251128674f, -0.38268343236508977f); // e^{-i pi/8}
    const ull STEPP = PKF(0.92387953251128674f,  0.38268343236508977f); // e^{+i pi/8}

    const float* xr = x + (size_t)blockIdx.x * NN;
    for (int idx = tid; idx < NN; idx += NT) smf[idx + (idx>>5)] = xr[idx];
    __syncthreads();

    ull xt[8];
    { ull cur = etaC0;                        // conj(eta)^n chain
#pragma unroll
      for (int t = 0; t < 8; t++){
          int n = n0 + 256*t;
          float v = smf[n + (n>>5)];
          xt[t] = pmul(PKF(v, v), cur);
          cur = pcmul(cur, STEPC);
      } }
    __syncthreads();

    ull xh[8];
    fwd2048(xt, xh, sm2, tws, tw2, T, lane, w);

    ull y[8];
#pragma unroll
    for (int v = 0; v < 8; v++) y[v] = 0ull;

#pragma unroll 1
    for (int jj = 0; jj < 2; jj++){
        const float2* __restrict__ HH = g_HH[jj];
        const float2* __restrict__ A  = g_A[jj];
        const float2* __restrict__ B  = g_B[jj];

        ull q[8];
#pragma unroll
        for (int v = 0; v < 8; v++){
            float2 h = HH[256*v + 32*w + lane];
            q[v] = pcmul(PKF(h.x, h.y), xh[v]);
        }

        ull zt[8];
        inv2048(q, zt, sm2, tws, tw2, T, lane, w);

        { ull cur = etaP0;                    // eta^n chain
#pragma unroll
          for (int t = 0; t < 8; t++){
              zt[t] = pcmul(cur, zt[t]);
              cur = pcmul(cur, STEPP);
          } }

        ull Wv[8];
        fwd2048(zt, Wv, sm2, tws, tw2, T, lane, w);

        __syncthreads();
#pragma unroll
        for (int v = 0; v < 8; v++)
            sm2[(v*8 + w)*33 + lane] = Wv[v];            // (v, c=lane, s=w)
        __syncthreads();
#pragma unroll
        for (int v = 0; v < 8; v++){
            int k  = 256*v + 8*lane + w;
            int kn = (NN - k) & (NN - 1);
            ull wp = sm2[((kn>>8)*8 + (kn&7))*33 + ((kn>>3)&31)];
            int fidx = 256*v + 32*w + lane;
            float2 av = A[fidx], bv = B[fidx];
            ull t1 = pcmul (PKF(av.x, av.y), Wv[v]);
            ull t2 = pcmulj(PKF(bv.x, bv.y), wp);
            y[v] = padd(y[v], padd(t1, t2));
        }
    }

    ull rt[8];
    inv2048(y, rt, sm2, tws, tw2, T, lane, w);

    __syncthreads();
#pragma unroll
    for (int t = 0; t < 8; t++){
        int n = n0 + 256*t;
        float rx, ry; UPK(rt[t], rx, ry);
        smf[n + (n>>5)] = rx * (1.f/(float)NN);
    }
    __syncthreads();

    float* orow = out + (size_t)blockIdx.x * NN;
    for (int idx = tid; idx < NN; idx += NT) orow[idx] = smf[idx + (idx>>5)];
}

// ---------------------------------------------------------------------------
extern "C" void kernel_launch(void* const* d_in, const int* in_sizes, int n_in,
                              void* d_out, int out_size)
{
    const float* x = (const float*)d_in[0];
    const float* G = (const float*)d_in[1];
    const float* H = (const float*)d_in[2];
    float* out = (float*)d_out;
    (void)in_sizes; (void)n_in; (void)out_size;

    precompute_kernel<<<2 * RR, NT>>>(G, H);
    combine_kernel<<<2, NT>>>();
    toeplitz_kernel<<<4096, NT>>>(x, out);
}

// round 9
// speedup vs baseline: 1.7729x; 1.7729x over previous
#include <cuda_runtime.h>
#include <cuda_bf16.h>

#define NN 2048
#define RR 4
#define NT 256
#define BR3(j) ((((j)&1)<<2) | ((j)&2) | (((j)&4)>>2))

// Precomputed filters, storage index fidx = 256v + 32s + c  (k = 256v + 8c + s)
__device__ float2 g_Ghat[RR][NN];
__device__ float2 g_Hhat[RR][NN];
__device__ float2 g_HH[2][NN];
__device__ float2 g_A [2][NN];
__device__ float2 g_B [2][NN];

__device__ __forceinline__ float2 cadd(float2 a, float2 b){ return make_float2(a.x+b.x, a.y+b.y); }
__device__ __forceinline__ float2 csub(float2 a, float2 b){ return make_float2(a.x-b.x, a.y-b.y); }
__device__ __forceinline__ float2 cmul(float2 a, float2 b){
    return make_float2(a.x*b.x - a.y*b.y, a.x*b.y + a.y*b.x);
}
__device__ __forceinline__ float2 cmulj(float2 a, float2 b){   // a * conj(b)
    return make_float2(a.x*b.x + a.y*b.y, a.y*b.x - a.x*b.y);
}
__device__ __forceinline__ float2 csqr(float2 a){ return make_float2(a.x*a.x - a.y*a.y, 2.f*a.x*a.y); }
__device__ __forceinline__ int br5(int x){ return (int)(__brev((unsigned)x) >> 27); }

__device__ __forceinline__ float2 shfl_xor_c(float2 v, int m){
    return make_float2(__shfl_xor_sync(0xffffffffu, v.x, m),
                       __shfl_xor_sync(0xffffffffu, v.y, m));
}

// Branch-free butterfly: out = p + s*v  (s = +1 low lanes, -1 high lanes)
__device__ __forceinline__ float2 bfly(float2 p, float2 v, float s){
    return make_float2(fmaf(s, v.x, p.x), fmaf(s, v.y, p.y));
}

// Per-lane twiddles: W_m = (lane&m)? w_m : (1,0);  s_m = (lane&m)? -1 : +1
struct LaneTw {
    float2 W16, W8, W4;
    float s16, s8, s4, s2, s1;
};

__device__ __forceinline__ LaneTw make_lane_tw(int lane){
    float s, c;
    sincospif((float)(lane & 15) * (1.f/16.f), &s, &c);
    float2 w16 = make_float2(c, -s);                        // e^{-i pi (lane&15)/16}
    float2 w8 = csqr(w16); if (lane & 8){ w8.x = -w8.x; w8.y = -w8.y; }
    float2 w4 = csqr(w8);  if (lane & 4){ w4.x = -w4.x; w4.y = -w4.y; }
    LaneTw T;
    T.W16 = (lane & 16) ? w16 : make_float2(1.f, 0.f);
    T.W8  = (lane & 8)  ? w8  : make_float2(1.f, 0.f);
    T.W4  = (lane & 4)  ? w4  : make_float2(1.f, 0.f);
    T.s16 = (lane & 16) ? -1.f : 1.f;
    T.s8  = (lane & 8)  ? -1.f : 1.f;
    T.s4  = (lane & 4)  ? -1.f : 1.f;
    T.s2  = (lane & 2)  ? -1.f : 1.f;
    T.s1  = (lane & 1)  ? -1.f : 1.f;
    return T;
}

// DIF FFT-32 across lanes; input natural (lane = time), output lane l holds X[br5(l)].
__device__ __forceinline__ float2 fft32_fwd(float2 v, const LaneTw& T, int lane){
    float2 p, t;
    p = shfl_xor_c(v, 16);
    t = bfly(p, v, T.s16);  v = cmul(t, T.W16);
    p = shfl_xor_c(v, 8);
    t = bfly(p, v, T.s8);   v = cmul(t, T.W8);
    p = shfl_xor_c(v, 4);
    t = bfly(p, v, T.s4);   v = cmul(t, T.W4);
    p = shfl_xor_c(v, 2);
    t = bfly(p, v, T.s2);
    v = ((lane & 3) == 3) ? make_float2(t.y, -t.x) : t;     // * -i on lanes 3 mod 4
    p = shfl_xor_c(v, 1);
    v = bfly(p, v, T.s1);
    return v;
}

// Exact unscaled inverse (input bit-reversed across lanes, output natural, x32).
__device__ __forceinline__ float2 fft32_inv(float2 v, const LaneTw& T, int lane){
    float2 p;
    p = shfl_xor_c(v, 1);
    v = bfly(p, v, T.s1);
    if ((lane & 3) == 3) v = make_float2(-v.y, v.x);        // * i
    p = shfl_xor_c(v, 2);
    v = bfly(p, v, T.s2);
    v = cmulj(v, T.W4);
    p = shfl_xor_c(v, 4);
    v = bfly(p, v, T.s4);
    v = cmulj(v, T.W8);
    p = shfl_xor_c(v, 8);
    v = bfly(p, v, T.s8);
    v = cmulj(v, T.W16);
    p = shfl_xor_c(v, 16);
    v = bfly(p, v, T.s16);
    return v;
}

// Register FFT-8, DIF, output reg j holds X8[br3(j)].
__device__ __forceinline__ void fft8_fwd(float2 r[8]){
    const float R2 = 0.70710678118654752440f;
    float2 a, d;
    a = r[0]; r[0] = cadd(a, r[4]); r[4] = csub(a, r[4]);
    a = r[1]; d = csub(a, r[5]); r[1] = cadd(a, r[5]);
              r[5] = make_float2((d.x + d.y)*R2, (d.y - d.x)*R2);      // * (R2,-R2)
    a = r[2]; d = csub(a, r[6]); r[2] = cadd(a, r[6]);
              r[6] = make_float2(d.y, -d.x);                            // * -i
    a = r[3]; d = csub(a, r[7]); r[3] = cadd(a, r[7]);
              r[7] = make_float2((d.y - d.x)*R2, -(d.x + d.y)*R2);      // * (-R2,-R2)
    a = r[0]; r[0] = cadd(a, r[2]); r[2] = csub(a, r[2]);
    a = r[1]; d = csub(a, r[3]); r[1] = cadd(a, r[3]); r[3] = make_float2(d.y, -d.x);
    a = r[4]; r[4] = cadd(a, r[6]); r[6] = csub(a, r[6]);
    a = r[5]; d = csub(a, r[7]); r[5] = cadd(a, r[7]); r[7] = make_float2(d.y, -d.x);
    a = r[0]; r[0] = cadd(a, r[1]); r[1] = csub(a, r[1]);
    a = r[2]; r[2] = cadd(a, r[3]); r[3] = csub(a, r[3]);
    a = r[4]; r[4] = cadd(a, r[5]); r[5] = csub(a, r[5]);
    a = r[6]; r[6] = cadd(a, r[7]); r[7] = csub(a, r[7]);
}

// Exact unscaled inverse of fft8_fwd (input br3 order, output natural, x8).
__device__ __forceinline__ void fft8_inv(float2 r[8]){
    const float R2 = 0.70710678118654752440f;
    float2 a, d;
    a = r[0]; r[0] = cadd(a, r[1]); r[1] = csub(a, r[1]);
    a = r[2]; r[2] = cadd(a, r[3]); r[3] = csub(a, r[3]);
    a = r[4]; r[4] = cadd(a, r[5]); r[5] = csub(a, r[5]);
    a = r[6]; r[6] = cadd(a, r[7]); r[7] = csub(a, r[7]);
    a = r[0]; r[0] = cadd(a, r[2]); r[2] = csub(a, r[2]);
    d = make_float2(-r[3].y, r[3].x); a = r[1]; r[1] = cadd(a, d); r[3] = csub(a, d);
    a = r[4]; r[4] = cadd(a, r[6]); r[6] = csub(a, r[6]);
    d = make_float2(-r[7].y, r[7].x); a = r[5]; r[5] = cadd(a, d); r[7] = csub(a, d);
    d = r[4];                                       a = r[0]; r[0] = cadd(a, d); r[4] = csub(a, d);
    d = make_float2((r[5].x - r[5].y)*R2, (r[5].x + r[5].y)*R2);     // * (R2, R2)
                                                    a = r[1]; r[1] = cadd(a, d); r[5] = csub(a, d);
    d = make_float2(-r[6].y, r[6].x);               a = r[2]; r[2] = cadd(a, d); r[6] = csub(a, d);
    d = make_float2(-(r[7].x + r[7].y)*R2, (r[7].x - r[7].y)*R2);    // * (-R2, R2)
                                                    a = r[3]; r[3] = cadd(a, d); r[7] = csub(a, d);
}

// ---------------------------------------------------------------------------
// Forward 2048: input xt[t] = time values at n = n0 + 256t (n0 = w + 8*lane);
// output xh[v] = X[k], k = 256v + 8*lane + w.  Uses sm2[2112] transpose buffer.
// ---------------------------------------------------------------------------
__device__ __forceinline__ void fwd2048(float2 xt[8], float2 xh[8], float2* sm2,
                                        const float2 tws[8], float2 tw2,
                                        const LaneTw& T, int lane, int w)
{
    fft8_fwd(xt);                              // reg j -> digit s = br3(j)
#pragma unroll
    for (int j = 1; j < 8; j++) xt[j] = cmul(xt[j], tws[BR3(j)]);
    int c = br5(lane);
    __syncthreads();                            // protect prior readers of sm2
#pragma unroll
    for (int j = 0; j < 8; j++){
        float2 v = fft32_fwd(xt[j], T, lane);   // over lanes, per s
        v = cmul(v, tw2);                       // w_256^{w*br5(lane)}
        sm2[(w*8 + BR3(j))*33 + c] = v;         // (s, c, r=w)
    }
    __syncthreads();
    float2 m[8];
#pragma unroll
    for (int rr = 0; rr < 8; rr++) m[rr] = sm2[(rr*8 + w)*33 + lane];  // role (s=w, c=lane)
    fft8_fwd(m);                                // reg j -> v = br3(j)
#pragma unroll
    for (int v = 0; v < 8; v++) xh[v] = m[BR3(v)];
}

// Exact unscaled inverse (x2048): input q[v] spectrum, output xt[t] time.
__device__ __forceinline__ void inv2048(float2 q[8], float2 xt[8], float2* sm2,
                                        const float2 tws[8], float2 tw2,
                                        const LaneTw& T, int lane, int w)
{
    float2 r[8];
#pragma unroll
    for (int j = 0; j < 8; j++) r[j] = q[BR3(j)];
    fft8_inv(r);                                // r[rr] -> value bound for warp rr
    __syncthreads();
#pragma unroll
    for (int rr = 0; rr < 8; rr++) sm2[(rr*8 + w)*33 + lane] = r[rr];  // (s=w, c=lane, r=rr)
    __syncthreads();
    int c = br5(lane);
    float2 rs[8];
#pragma unroll
    for (int s = 0; s < 8; s++){
        float2 v = sm2[(w*8 + s)*33 + c];       // (s, c=br5(lane), r=w)
        v = cmulj(v, tw2);
        rs[s] = fft32_inv(v, T, lane);
    }
#pragma unroll
    for (int j = 0; j < 8; j++)
        xt[j] = (BR3(j) == 0) ? rs[0] : cmulj(rs[BR3(j)], tws[BR3(j)]);
    fft8_inv(xt);                               // xt[t], total x2048
}

// ---------------------------------------------------------------------------
__global__ void __launch_bounds__(NT)
precompute_kernel(const float* __restrict__ G, const float* __restrict__ H)
{
    __shared__ float2 sm2[2112];
    float* smf = (float*)sm2;
    int tid = threadIdx.x, lane = tid & 31, w = tid >> 5;
    int n0 = w + 8*lane;
    LaneTw T = make_lane_tw(lane);
    float2 tws[8];
    { float s, c; sincospif((float)n0*(1.f/1024.f), &s, &c);
      float2 b = make_float2(c, -s);
      tws[0] = make_float2(1.f, 0.f); tws[1] = b;
#pragma unroll
      for (int j = 2; j < 8; j++) tws[j] = cmul(tws[j-1], b); }
    float2 tw2;
    { float s, c; sincospif((float)(w*br5(lane))*(1.f/128.f), &s, &c); tw2 = make_float2(c, -s); }

    int wb = blockIdx.x;
    const float* src = (wb < RR) ? (G + wb*NN) : (H + (wb-RR)*NN);
    for (int idx = tid; idx < NN; idx += NT) smf[idx + (idx>>5)] = src[idx];
    __syncthreads();

    float2 xt[8];
    if (wb < RR){
#pragma unroll
        for (int t = 0; t < 8; t++){
            int n = n0 + 256*t;
            xt[t] = make_float2(smf[n + (n>>5)], 0.f);
        }
    } else {
#pragma unroll
        for (int t = 0; t < 8; t++){
            int n = n0 + 256*t;
            int j = (NN - n) & (NN - 1);
            float hv = smf[j + (j>>5)];
            float s, c; sincospif((float)j*(1.f/(float)NN), &s, &c);   // eta^j
            xt[t] = make_float2(hv*c, hv*s);
        }
    }
    __syncthreads();

    float2 xh[8];
    fwd2048(xt, xh, sm2, tws, tw2, T, lane, w);

    float2* dst = (wb < RR) ? g_Ghat[wb] : g_Hhat[wb - RR];
#pragma unroll
    for (int v = 0; v < 8; v++) dst[256*v + 32*w + lane] = xh[v];
}

__global__ void __launch_bounds__(NT)
combine_kernel()
{
    int j = blockIdx.x, tid = threadIdx.x;
    const float cs = 0.5f / (float)NN;
    for (int k = tid; k < NN; k += NT){
        float2 g0 = g_Ghat[2*j][k], g1 = g_Ghat[2*j+1][k];
        float2 h0 = g_Hhat[2*j][k], h1 = g_Hhat[2*j+1][k];
        g_A[j][k]  = make_float2((g0.x + g1.y) * cs, (g0.y - g1.x) * cs);
        g_B[j][k]  = make_float2((g0.x - g1.y) * cs, (g0.y + g1.x) * cs);
        g_HH[j][k] = make_float2(h0.x - h1.y,        h0.y + h1.x);
    }
}

// ---------------------------------------------------------------------------
__global__ void __launch_bounds__(NT)
toeplitz_kernel(const float* __restrict__ x, float* __restrict__ out)
{
    __shared__ float2 sm2[2112];
    float* smf = (float*)sm2;
    int tid = threadIdx.x, lane = tid & 31, w = tid >> 5;
    int n0 = w + 8*lane;
    LaneTw T = make_lane_tw(lane);

    float2 tws[8];
    { float s, c; sincospif((float)n0*(1.f/1024.f), &s, &c);
      float2 b = make_float2(c, -s);
      tws[0] = make_float2(1.f, 0.f); tws[1] = b;
#pragma unroll
      for (int j = 2; j < 8; j++) tws[j] = cmul(tws[j-1], b); }
    float2 tw2;
    { float s, c; sincospif((float)(w*br5(lane))*(1.f/128.f), &s, &c); tw2 = make_float2(c, -s); }
    float2 etaC0;
    { float s, c; sincospif((float)n0*(1.f/(float)NN), &s, &c); etaC0 = make_float2(c, -s); }
    const float2 STEPC = make_float2(0.92387953251128674f, -0.38268343236508977f); // e^{-i pi/8}
    const float2 STEPP = make_float2(0.92387953251128674f,  0.38268343236508977f); // e^{+i pi/8}

    const float* xr = x + (size_t)blockIdx.x * NN;
    for (int idx = tid; idx < NN; idx += NT) smf[idx + (idx>>5)] = xr[idx];
    __syncthreads();

    float2 xt[8];
    { float2 cur = etaC0;                     // conj(eta)^n chain
#pragma unroll
      for (int t = 0; t < 8; t++){
          int n = n0 + 256*t;
          float v = smf[n + (n>>5)];
          xt[t] = make_float2(v*cur.x, v*cur.y);
          cur = cmul(cur, STEPC);
      } }
    __syncthreads();

    float2 xh[8];
    fwd2048(xt, xh, sm2, tws, tw2, T, lane, w);

    float2 y[8];
#pragma unroll
    for (int v = 0; v < 8; v++) y[v] = make_float2(0.f, 0.f);

#pragma unroll 1
    for (int jj = 0; jj < 2; jj++){
        const float2* __restrict__ HH = g_HH[jj];
        const float2* __restrict__ A  = g_A[jj];
        const float2* __restrict__ B  = g_B[jj];

        float2 q[8];
#pragma unroll
        for (int v = 0; v < 8; v++)
            q[v] = cmul(HH[256*v + 32*w + lane], xh[v]);

        float2 zt[8];
        inv2048(q, zt, sm2, tws, tw2, T, lane, w);

        { float2 cur = make_float2(etaC0.x, -etaC0.y);   // eta^{n0}
#pragma unroll
          for (int t = 0; t < 8; t++){
              zt[t] = cmul(cur, zt[t]);
              cur = cmul(cur, STEPP);
          } }

        float2 Wv[8];
        fwd2048(zt, Wv, sm2, tws, tw2, T, lane, w);

        __syncthreads();
#pragma unroll
        for (int v = 0; v < 8; v++)
            sm2[(v*8 + w)*33 + lane] = Wv[v];            // (v, c=lane, s=w)
        __syncthreads();
#pragma unroll
        for (int v = 0; v < 8; v++){
            int k  = 256*v + 8*lane + w;
            int kn = (NN - k) & (NN - 1);
            float2 wp = sm2[((kn>>8)*8 + (kn&7))*33 + ((kn>>3)&31)];
            int fidx = 256*v + 32*w + lane;
            y[v] = cadd(y[v], cadd(cmul(A[fidx], Wv[v]), cmulj(B[fidx], wp)));
        }
    }

    float2 rt[8];
    inv2048(y, rt, sm2, tws, tw2, T, lane, w);

    __syncthreads();
#pragma unroll
    for (int t = 0; t < 8; t++){
        int n = n0 + 256*t;
        smf[n + (n>>5)] = rt[t].x * (1.f/(float)NN);
    }
    __syncthreads();

    float* orow = out + (size_t)blockIdx.x * NN;
    for (int idx = tid; idx < NN; idx += NT) orow[idx] = smf[idx + (idx>>5)];
}

// ---------------------------------------------------------------------------
extern "C" void kernel_launch(void* const* d_in, const int* in_sizes, int n_in,
                              void* d_out, int out_size)
{
    const float* x = (const float*)d_in[0];
    const float* G = (const float*)d_in[1];
    const float* H = (const float*)d_in[2];
    float* out = (float*)d_out;
    (void)in_sizes; (void)n_in; (void)out_size;

    precompute_kernel<<<2 * RR, NT>>>(G, H);
    combine_kernel<<<2, NT>>>();
    toeplitz_kernel<<<4096, NT>>>(x, out);
}

// round 10
// speedup vs baseline: 1.9158x; 1.0806x over previous
#include <cuda_runtime.h>
#include <cuda_bf16.h>

#define NN 2048
#define RR 4
#define NT 256
#define BR3(j) ((((j)&1)<<2) | ((j)&2) | (((j)&4)>>2))

// Filters, storage index fidx = 256v + 32s + c  (frequency k = 256v + 8c + s)
__device__ float2 g_Ghat[RR][NN];
__device__ float2 g_Hhat[RR][NN];
__device__ float2 g_HH[2][NN];
__device__ float2 g_A [2][NN];
__device__ float2 g_B [2][NN];

__device__ __forceinline__ float2 cadd(float2 a, float2 b){ return make_float2(a.x+b.x, a.y+b.y); }
__device__ __forceinline__ float2 csub(float2 a, float2 b){ return make_float2(a.x-b.x, a.y-b.y); }
__device__ __forceinline__ float2 cmul(float2 a, float2 b){
    return make_float2(a.x*b.x - a.y*b.y, a.x*b.y + a.y*b.x);
}
__device__ __forceinline__ float2 cmulj(float2 a, float2 b){   // a * conj(b)
    return make_float2(a.x*b.x + a.y*b.y, a.y*b.x - a.x*b.y);
}
__device__ __forceinline__ float2 csqr(float2 a){ return make_float2(a.x*a.x - a.y*a.y, 2.f*a.x*a.y); }
__device__ __forceinline__ int br5(int x){ return (int)(__brev((unsigned)x) >> 27); }

__device__ __forceinline__ float2 shfl_xor_c(float2 v, int m){
    return make_float2(__shfl_xor_sync(0xffffffffu, v.x, m),
                       __shfl_xor_sync(0xffffffffu, v.y, m));
}
__device__ __forceinline__ float2 bfly(float2 p, float2 v, float s){
    return make_float2(fmaf(s, v.x, p.x), fmaf(s, v.y, p.y));
}

struct LaneTw {
    float2 W16, W8, W4;
    float s16, s8, s4, s2, s1;
};

__device__ __forceinline__ LaneTw make_lane_tw(int lane){
    float s, c;
    sincospif((float)(lane & 15) * (1.f/16.f), &s, &c);
    float2 w16 = make_float2(c, -s);
    float2 w8 = csqr(w16); if (lane & 8){ w8.x = -w8.x; w8.y = -w8.y; }
    float2 w4 = csqr(w8);  if (lane & 4){ w4.x = -w4.x; w4.y = -w4.y; }
    LaneTw T;
    T.W16 = (lane & 16) ? w16 : make_float2(1.f, 0.f);
    T.W8  = (lane & 8)  ? w8  : make_float2(1.f, 0.f);
    T.W4  = (lane & 4)  ? w4  : make_float2(1.f, 0.f);
    T.s16 = (lane & 16) ? -1.f : 1.f;
    T.s8  = (lane & 8)  ? -1.f : 1.f;
    T.s4  = (lane & 4)  ? -1.f : 1.f;
    T.s2  = (lane & 2)  ? -1.f : 1.f;
    T.s1  = (lane & 1)  ? -1.f : 1.f;
    return T;
}

__device__ __forceinline__ float2 fft32_fwd(float2 v, const LaneTw& T, int lane){
    float2 p, t;
    p = shfl_xor_c(v, 16);
    t = bfly(p, v, T.s16);  v = cmul(t, T.W16);
    p = shfl_xor_c(v, 8);
    t = bfly(p, v, T.s8);   v = cmul(t, T.W8);
    p = shfl_xor_c(v, 4);
    t = bfly(p, v, T.s4);   v = cmul(t, T.W4);
    p = shfl_xor_c(v, 2);
    t = bfly(p, v, T.s2);
    v = ((lane & 3) == 3) ? make_float2(t.y, -t.x) : t;
    p = shfl_xor_c(v, 1);
    v = bfly(p, v, T.s1);
    return v;
}

__device__ __forceinline__ float2 fft32_inv(float2 v, const LaneTw& T, int lane){
    float2 p;
    p = shfl_xor_c(v, 1);
    v = bfly(p, v, T.s1);
    if ((lane & 3) == 3) v = make_float2(-v.y, v.x);
    p = shfl_xor_c(v, 2);
    v = bfly(p, v, T.s2);
    v = cmulj(v, T.W4);
    p = shfl_xor_c(v, 4);
    v = bfly(p, v, T.s4);
    v = cmulj(v, T.W8);
    p = shfl_xor_c(v, 8);
    v = bfly(p, v, T.s8);
    v = cmulj(v, T.W16);
    p = shfl_xor_c(v, 16);
    v = bfly(p, v, T.s16);
    return v;
}

__device__ __forceinline__ void fft8_fwd(float2 r[8]){
    const float R2 = 0.70710678118654752440f;
    float2 a, d;
    a = r[0]; r[0] = cadd(a, r[4]); r[4] = csub(a, r[4]);
    a = r[1]; d = csub(a, r[5]); r[1] = cadd(a, r[5]);
              r[5] = make_float2((d.x + d.y)*R2, (d.y - d.x)*R2);
    a = r[2]; d = csub(a, r[6]); r[2] = cadd(a, r[6]);
              r[6] = make_float2(d.y, -d.x);
    a = r[3]; d = csub(a, r[7]); r[3] = cadd(a, r[7]);
              r[7] = make_float2((d.y - d.x)*R2, -(d.x + d.y)*R2);
    a = r[0]; r[0] = cadd(a, r[2]); r[2] = csub(a, r[2]);
    a = r[1]; d = csub(a, r[3]); r[1] = cadd(a, r[3]); r[3] = make_float2(d.y, -d.x);
    a = r[4]; r[4] = cadd(a, r[6]); r[6] = csub(a, r[6]);
    a = r[5]; d = csub(a, r[7]); r[5] = cadd(a, r[7]); r[7] = make_float2(d.y, -d.x);
    a = r[0]; r[0] = cadd(a, r[1]); r[1] = csub(a, r[1]);
    a = r[2]; r[2] = cadd(a, r[3]); r[3] = csub(a, r[3]);
    a = r[4]; r[4] = cadd(a, r[5]); r[5] = csub(a, r[5]);
    a = r[6]; r[6] = cadd(a, r[7]); r[7] = csub(a, r[7]);
}

__device__ __forceinline__ void fft8_inv(float2 r[8]){
    const float R2 = 0.70710678118654752440f;
    float2 a, d;
    a = r[0]; r[0] = cadd(a, r[1]); r[1] = csub(a, r[1]);
    a = r[2]; r[2] = cadd(a, r[3]); r[3] = csub(a, r[3]);
    a = r[4]; r[4] = cadd(a, r[5]); r[5] = csub(a, r[5]);
    a = r[6]; r[6] = cadd(a, r[7]); r[7] = csub(a, r[7]);
    a = r[0]; r[0] = cadd(a, r[2]); r[2] = csub(a, r[2]);
    d = make_float2(-r[3].y, r[3].x); a = r[1]; r[1] = cadd(a, d); r[3] = csub(a, d);
    a = r[4]; r[4] = cadd(a, r[6]); r[6] = csub(a, r[6]);
    d = make_float2(-r[7].y, r[7].x); a = r[5]; r[5] = cadd(a, d); r[7] = csub(a, d);
    d = r[4];                                       a = r[0]; r[0] = cadd(a, d); r[4] = csub(a, d);
    d = make_float2((r[5].x - r[5].y)*R2, (r[5].x + r[5].y)*R2);
                                                    a = r[1]; r[1] = cadd(a, d); r[5] = csub(a, d);
    d = make_float2(-r[6].y, r[6].x);               a = r[2]; r[2] = cadd(a, d); r[6] = csub(a, d);
    d = make_float2(-(r[7].x + r[7].y)*R2, (r[7].x - r[7].y)*R2);
                                                    a = r[3]; r[3] = cadd(a, d); r[7] = csub(a, d);
}

// Forward 2048: xt[t] at n = n0 + 256t (n0 = w + 8*lane) -> xh[v] = X[256v+8*lane+w]
__device__ __forceinline__ void fwd2048(float2 xt[8], float2 xh[8], float2* sm2,
                                        const float2 tws[8], float2 tw2,
                                        const LaneTw& T, int lane, int w)
{
    fft8_fwd(xt);
#pragma unroll
    for (int j = 1; j < 8; j++) xt[j] = cmul(xt[j], tws[BR3(j)]);
    int c = br5(lane);
    __syncthreads();
#pragma unroll
    for (int j = 0; j < 8; j++){
        float2 v = fft32_fwd(xt[j], T, lane);
        v = cmul(v, tw2);
        sm2[(w*8 + BR3(j))*33 + c] = v;
    }
    __syncthreads();
    float2 m[8];
#pragma unroll
    for (int rr = 0; rr < 8; rr++) m[rr] = sm2[(rr*8 + w)*33 + lane];
    fft8_fwd(m);
#pragma unroll
    for (int v = 0; v < 8; v++) xh[v] = m[BR3(v)];
}

// Inverse (unscaled x2048): q[v] spectrum -> xt[t] time
__device__ __forceinline__ void inv2048(float2 q[8], float2 xt[8], float2* sm2,
                                        const float2 tws[8], float2 tw2,
                                        const LaneTw& T, int lane, int w)
{
    float2 r[8];
#pragma unroll
    for (int j = 0; j < 8; j++) r[j] = q[BR3(j)];
    fft8_inv(r);
    __syncthreads();
#pragma unroll
    for (int rr = 0; rr < 8; rr++) sm2[(rr*8 + w)*33 + lane] = r[rr];
    __syncthreads();
    int c = br5(lane);
    float2 rs[8];
#pragma unroll
    for (int s = 0; s < 8; s++){
        float2 v = sm2[(w*8 + s)*33 + c];
        v = cmulj(v, tw2);
        rs[s] = fft32_inv(v, T, lane);
    }
#pragma unroll
    for (int j = 0; j < 8; j++)
        xt[j] = (BR3(j) == 0) ? rs[0] : cmulj(rs[BR3(j)], tws[BR3(j)]);
    fft8_inv(xt);
}

__device__ __forceinline__ void setup_tws(float2 tws[8], float2& tw2, int n0, int lane, int w){
    float s, c;
    sincospif((float)n0*(1.f/1024.f), &s, &c);
    float2 b = make_float2(c, -s);
    tws[0] = make_float2(1.f, 0.f); tws[1] = b;
#pragma unroll
    for (int j = 2; j < 8; j++) tws[j] = cmul(tws[j-1], b);
    sincospif((float)(w*br5(lane))*(1.f/128.f), &s, &c);
    tw2 = make_float2(c, -s);
}

// ---------------------------------------------------------------------------
// Merged precompute + combine: 2 blocks; block j computes its 4 spectra
// sequentially, then builds g_HH/g_A/g_B for pair j. (2 launches total/call.)
// ---------------------------------------------------------------------------
__global__ void __launch_bounds__(NT)
prep_kernel(const float* __restrict__ G, const float* __restrict__ H)
{
    __shared__ float2 sm2[2112];
    float* smf = (float*)sm2;
    int tid = threadIdx.x, lane = tid & 31, w = tid >> 5;
    int n0 = w + 8*lane;
    int jp = blockIdx.x;
    LaneTw T = make_lane_tw(lane);
    float2 tws[8], tw2;
    setup_tws(tws, tw2, n0, lane, w);

#pragma unroll 1
    for (int wb = 0; wb < 4; wb++){
        const float* src = (wb < 2) ? (G + (2*jp + wb)*NN) : (H + (2*jp + wb - 2)*NN);
        for (int idx = tid; idx < NN; idx += NT) smf[idx + (idx>>5)] = src[idx];
        __syncthreads();

        float2 xt[8];
        if (wb < 2){
#pragma unroll
            for (int t = 0; t < 8; t++){
                int n = n0 + 256*t;
                xt[t] = make_float2(smf[n + (n>>5)], 0.f);
            }
        } else {
#pragma unroll
            for (int t = 0; t < 8; t++){
                int n = n0 + 256*t;
                int j = (NN - n) & (NN - 1);
                float hv = smf[j + (j>>5)];
                float s, c; sincospif((float)j*(1.f/(float)NN), &s, &c);
                xt[t] = make_float2(hv*c, hv*s);
            }
        }
        __syncthreads();

        float2 xh[8];
        fwd2048(xt, xh, sm2, tws, tw2, T, lane, w);

        float2* dst = (wb < 2) ? g_Ghat[2*jp + wb] : g_Hhat[2*jp + wb - 2];
#pragma unroll
        for (int v = 0; v < 8; v++) dst[256*v + 32*w + lane] = xh[v];
        __syncthreads();              // drain sm2 reads + make globals visible
    }

    const float cs = 0.5f / (float)NN;
    for (int k = tid; k < NN; k += NT){
        float2 g0 = g_Ghat[2*jp][k], g1 = g_Ghat[2*jp+1][k];
        float2 h0 = g_Hhat[2*jp][k], h1 = g_Hhat[2*jp+1][k];
        g_A[jp][k]  = make_float2((g0.x + g1.y) * cs, (g0.y - g1.x) * cs);
        g_B[jp][k]  = make_float2((g0.x - g1.y) * cs, (g0.y + g1.x) * cs);
        g_HH[jp][k] = make_float2(h0.x - h1.y,        h0.y + h1.x);
    }
}

// ---------------------------------------------------------------------------
// Main: TWO rows per CTA.  dyn smem: sm2[2112] | Xa[2048] | Xb[2048] = 48.5KB
// ---------------------------------------------------------------------------
__global__ void __launch_bounds__(NT)
toeplitz_kernel(const float* __restrict__ x, float* __restrict__ out)
{
    extern __shared__ float2 smx[];
    float2* sm2  = smx;
    float2* Xa_s = smx + 2112;
    float2* Xb_s = smx + 4160;
    float* smfA = (float*)Xa_s;
    float* smfB = (float*)Xb_s;

    int tid = threadIdx.x, lane = tid & 31, w = tid >> 5;
    int n0 = w + 8*lane;
    LaneTw T = make_lane_tw(lane);
    float2 tws[8], tw2;
    setup_tws(tws, tw2, n0, lane, w);
    float2 etaC0;
    { float s, c; sincospif((float)n0*(1.f/(float)NN), &s, &c); etaC0 = make_float2(c, -s); }
    const float2 STEPC = make_float2(0.92387953251128674f, -0.38268343236508977f); // e^{-i pi/8}
    const float2 STEPP = make_float2(0.92387953251128674f,  0.38268343236508977f); // e^{+i pi/8}

    size_t row = (size_t)blockIdx.x * 2;
    const float* xa = x + row * NN;
    const float* xb = xa + NN;

    for (int idx = tid; idx < NN; idx += NT){
        smfA[idx + (idx>>5)] = xa[idx];
        smfB[idx + (idx>>5)] = xb[idx];
    }
    __syncthreads();

    // packed z = (x_a + i x_b) * conj(eta)^n
    float2 xt[8];
    { float2 cur = etaC0;
#pragma unroll
      for (int t = 0; t < 8; t++){
          int n = n0 + 256*t;
          float va = smfA[n + (n>>5)];
          float vb = smfB[n + (n>>5)];
          xt[t] = cmul(make_float2(va, vb), cur);
          cur = cmul(cur, STEPC);
      } }

    float2 zh[8];
    fwd2048(xt, zh, sm2, tws, tw2, T, lane, w);   // leading sync drains smf reads

    // store Zhat by frequency digits (same cells this thread just read: no sync)
#pragma unroll
    for (int v = 0; v < 8; v++) sm2[(v*8 + w)*33 + lane] = zh[v];
    __syncthreads();

    // split: Ma = (Z + conj(Z[2047-k]))/2 ; Mb = (Z - conj(Z[2047-k]))/2i
#pragma unroll
    for (int v = 0; v < 8; v++){
        int k  = 256*v + 8*lane + w;
        int kn = 2047 - k;
        float2 zn = sm2[((kn>>8)*8 + (kn&7))*33 + ((kn>>3)&31)];
        zn.y = -zn.y;                                  // conj
        float2 Ma = make_float2(0.5f*(zh[v].x + zn.x), 0.5f*(zh[v].y + zn.y));
        float2 D  = csub(zh[v], zn);
        float2 Mb = make_float2(0.5f*D.y, -0.5f*D.x);  // D / (2i)
        int fidx = 256*v + 32*w + lane;
        Xa_s[fidx] = Ma;
        Xb_s[fidx] = Mb;
    }
    __syncthreads();

    float2 ya[8], yb[8];
#pragma unroll
    for (int v = 0; v < 8; v++){ ya[v] = make_float2(0.f,0.f); yb[v] = make_float2(0.f,0.f); }

#pragma unroll
    for (int rs = 0; rs < 2; rs++){
        const float2* __restrict__ Xs = rs ? Xb_s : Xa_s;
#pragma unroll 1
        for (int jj = 0; jj < 2; jj++){
            const float2* __restrict__ HH = g_HH[jj];
            const float2* __restrict__ A  = g_A[jj];
            const float2* __restrict__ B  = g_B[jj];

            float2 q[8];
#pragma unroll
            for (int v = 0; v < 8; v++){
                int fidx = 256*v + 32*w + lane;
                q[v] = cmul(HH[fidx], Xs[fidx]);
            }

            float2 zt[8];
            inv2048(q, zt, sm2, tws, tw2, T, lane, w);

            { float2 cur = make_float2(etaC0.x, -etaC0.y);   // eta^n chain
#pragma unroll
              for (int t = 0; t < 8; t++){
                  zt[t] = cmul(cur, zt[t]);
                  cur = cmul(cur, STEPP);
              } }

            float2 Wv[8];
            fwd2048(zt, Wv, sm2, tws, tw2, T, lane, w);

            __syncthreads();
#pragma unroll
            for (int v = 0; v < 8; v++)
                sm2[(v*8 + w)*33 + lane] = Wv[v];
            __syncthreads();
#pragma unroll
            for (int v = 0; v < 8; v++){
                int k  = 256*v + 8*lane + w;
                int kn = (NN - k) & (NN - 1);
                float2 wp = sm2[((kn>>8)*8 + (kn&7))*33 + ((kn>>3)&31)];
                int fidx = 256*v + 32*w + lane;
                float2 acc = cadd(cmul(A[fidx], Wv[v]), cmulj(B[fidx], wp));
                if (rs == 0) ya[v] = cadd(ya[v], acc);
                else         yb[v] = cadd(yb[v], acc);
            }
        }
    }

    // P = Yhat_a + i*Yhat_b ; one packed inverse gives both (real) output rows
    float2 P[8];
#pragma unroll
    for (int v = 0; v < 8; v++)
        P[v] = make_float2(ya[v].x - yb[v].y, ya[v].y + yb[v].x);

    float2 rt[8];
    inv2048(P, rt, sm2, tws, tw2, T, lane, w);

    __syncthreads();
#pragma unroll
    for (int t = 0; t < 8; t++){
        int n = n0 + 256*t;
        smfA[n + (n>>5)] = rt[t].x * (1.f/(float)NN);
        smfB[n + (n>>5)] = rt[t].y * (1.f/(float)NN);
    }
    __syncthreads();

    float* oa = out + row * NN;
    float* ob = oa + NN;
    for (int idx = tid; idx < NN; idx += NT){
        oa[idx] = smfA[idx + (idx>>5)];
        ob[idx] = smfB[idx + (idx>>5)];
    }
}

// ---------------------------------------------------------------------------
extern "C" void kernel_launch(void* const* d_in, const int* in_sizes, int n_in,
                              void* d_out, int out_size)
{
    const float* x = (const float*)d_in[0];
    const float* G = (const float*)d_in[1];
    const float* H = (const float*)d_in[2];
    float* out = (float*)d_out;
    (void)in_sizes; (void)n_in; (void)out_size;

    size_t smem = (size_t)(2112 + 2048 + 2048) * sizeof(float2);   // 49,664 B
    cudaFuncSetAttribute(toeplitz_kernel,
                         cudaFuncAttributeMaxDynamicSharedMemorySize, (int)smem);

    prep_kernel<<<2, NT>>>(G, H);
    toeplitz_kernel<<<2048, NT, smem>>>(x, out);
}